// round 7
// baseline (speedup 1.0000x reference)
#include <cuda_runtime.h>
#include <cuda_bf16.h>

// Problem shape (fixed by the dataset)
#define BATCH 128
#define SEQLEN 1024
#define TAG 128
#define MID 512           // forward covers steps 1..MID, backward MID+1..SEQLEN-1

// Scratch (allocation-free rule: __device__ globals)
__device__ float g_logZ[BATCH];
__device__ float g_score[BATCH];

// ---------------- packed f32x2 helpers (Blackwell FFMA2) ----------------
__device__ __forceinline__ unsigned long long pack_f32x2(float lo, float hi) {
    unsigned long long r;
    asm("mov.b64 %0, {%1, %2};" : "=l"(r) : "f"(lo), "f"(hi));
    return r;
}
__device__ __forceinline__ void unpack_f32x2(float& lo, float& hi, unsigned long long v) {
    asm("mov.b64 {%0, %1}, %2;" : "=f"(lo), "=f"(hi) : "l"(v));
}
__device__ __forceinline__ unsigned long long fma2(unsigned long long a,
                                                   unsigned long long b,
                                                   unsigned long long c) {
    unsigned long long d;
    asm("fma.rn.f32x2 %0, %1, %2, %3;" : "=l"(d) : "l"(a), "l"(b), "l"(c));
    return d;
}
__device__ __forceinline__ unsigned long long add2(unsigned long long a,
                                                   unsigned long long b) {
    unsigned long long d;
    asm("add.rn.f32x2 %0, %1, %2;" : "=l"(d) : "l"(a), "l"(b));
    return d;
}

// Named barrier over one 128-thread half (ids 1 and 2).
__device__ __forceinline__ void half_sync(int barid) {
    asm volatile("bar.sync %0, %1;" :: "r"(barid), "r"(128) : "memory");
}

// shared 128-wide dot: s_t = sum_u vec[u] * w2[u/2] (packed), vec in smem.
__device__ __forceinline__ float dot128(const float* __restrict__ vec,
                                        const unsigned long long (&w2)[64]) {
    unsigned long long acc0 = 0ull, acc1 = 0ull, acc2 = 0ull, acc3 = 0ull;
    const ulonglong2* pp = reinterpret_cast<const ulonglong2*>(vec);
#pragma unroll
    for (int k = 0; k < 16; k++) {
        ulonglong2 v0 = pp[2 * k];
        ulonglong2 v1 = pp[2 * k + 1];
        acc0 = fma2(v0.x, w2[4 * k + 0], acc0);
        acc1 = fma2(v0.y, w2[4 * k + 1], acc1);
        acc2 = fma2(v1.x, w2[4 * k + 2], acc2);
        acc3 = fma2(v1.y, w2[4 * k + 3], acc3);
    }
    unsigned long long accA = add2(add2(acc0, acc1), add2(acc2, acc3));
    float slo, shi;
    unpack_f32x2(slo, shi, accA);
    return slo + shi;
}

// ---------------- forward step: alpha' = m*(alpha@EA)*ey + (1-m)*alpha ------
// RENORM: exact power-of-2 rescale once per 4 steps (range-safe: growth stays
// within [2^-60, 2^60] between renorms).
template <int SLOT, int BUF, bool RENORM>
__device__ __forceinline__ void fwd_step(
    int i, int t, float& alpha, int& kacc,
    float (&eyp)[4], float (&mr)[4],
    const float* __restrict__ yprow, const float* __restrict__ mrow,
    const unsigned long long (&ea2)[64],
    float (*pb)[TAG], float* sb)
{
    pb[BUF][t] = alpha;
    if (RENORM && t == 0) sb[0] = alpha;
    half_sync(1);

    float invc = 1.0f;
    if (RENORM) {
        int kb = (__float_as_int(sb[0]) >> 23) & 0xff;
        invc = __int_as_float((254 - kb) << 23);
        kacc += 127 - kb;
    }

    // prefetch row i+4 (consumed 4 steps from now); exp off the serial chain
    float eyp_n = 0.0f, m_n = 1.0f;
    if (i + 4 <= MID) {
        eyp_n = __expf(__ldg(yprow + (i + 4) * TAG));
        m_n   = __ldg(mrow + (i + 4));
    }

    float s = dot128(&pb[BUF][0], ea2);

    float cand = s * eyp[SLOT];
    if (RENORM) {
        alpha = (mr[SLOT] > 0.5f) ? cand * invc : alpha * invc;
    } else {
        alpha = (mr[SLOT] > 0.5f) ? cand : alpha;
    }
    eyp[SLOT] = eyp_n;
    mr[SLOT]  = m_n;
}

// ---------------- backward step: beta' = m*(EA@(ey.*beta)) + (1-m)*beta -----
// publishes c = ey.*beta; thread t holds EA row t packed in ear2.
template <int SLOT, int BUF, bool RENORM>
__device__ __forceinline__ void bwd_step(
    int i, int t, float& beta, int& kacc,
    float (&eyp)[4], float (&mr)[4],
    const float* __restrict__ yprow, const float* __restrict__ mrow,
    const unsigned long long (&ear2)[64],
    float (*pb)[TAG], float* sb)
{
    float c = beta * eyp[SLOT];
    pb[BUF][t] = c;
    if (RENORM && t == 0) sb[0] = c;
    half_sync(2);

    float invc = 1.0f;
    if (RENORM) {
        int kb = (__float_as_int(sb[0]) >> 23) & 0xff;
        invc = __int_as_float((254 - kb) << 23);
        kacc += 127 - kb;
    }

    // prefetch row i-4 (consumed 4 steps from now)
    float eyp_n = 0.0f, m_n = 1.0f;
    if (i - 4 > MID) {
        eyp_n = __expf(__ldg(yprow + (i - 4) * TAG));
        m_n   = __ldg(mrow + (i - 4));
    }

    float s = dot128(&pb[BUF][0], ear2);

    if (RENORM) {
        beta = ((mr[SLOT] > 0.5f) ? s : beta) * invc;
    } else {
        beta = (mr[SLOT] > 0.5f) ? s : beta;
    }
    eyp[SLOT] = eyp_n;
    mr[SLOT]  = m_n;
}

// ---------------- bidirectional logZ kernel: 1 CTA (256 thr) per batch -----
// Warps 0-3: forward recurrence (EA columns in regs). Warps 4-7: backward
// (EA rows in regs). Halves are decoupled via named barriers; serial depth
// drops from 1023 to 512 steps. Z = sum_t a_mid[t] * b_mid[t].
__global__ void __launch_bounds__(256, 1)
crf_forward_kernel(const float* __restrict__ y_pred,
                   const float* __restrict__ mask,
                   const float* __restrict__ A)
{
    const int tid = threadIdx.x;
    const int sub = tid >> 7;            // 0 = forward, 1 = backward
    const int t   = tid & (TAG - 1);
    const int b   = blockIdx.x;

    __shared__ __align__(16) float pbuf[2][2][TAG];  // [sub][buf][tag]
    __shared__ float sbroad[2][1];
    __shared__ int   skacc[2];
    float (*pb)[TAG] = pbuf[sub];
    float* sb = sbroad[sub];

    const float* yprow = y_pred + (size_t)b * SEQLEN * TAG + t;
    const float* mrow  = mask + (size_t)b * SEQLEN;

    if (sub == 0) {
        // ===================== FORWARD half: steps 1..512 ====================
        unsigned long long ea2[64];           // EA column t, packed along u
#pragma unroll
        for (int k = 0; k < 64; k++) {
            float e0 = __expf(__ldg(A + (2 * k)     * TAG + t));
            float e1 = __expf(__ldg(A + (2 * k + 1) * TAG + t));
            ea2[k] = pack_f32x2(e0, e1);
        }

        float alpha = __expf(__ldg(yprow));   // alpha_0 = e^{yp_0}
        int kacc = 0;

        float eyp[4], mr[4];
#pragma unroll
        for (int j = 0; j < 4; j++) {
            eyp[j] = __expf(__ldg(yprow + (1 + j) * TAG));
            mr[j]  = __ldg(mrow + (1 + j));
        }

        // 512 steps = 128 groups of 4, exactly
        for (int i = 1; i + 3 <= MID; i += 4) {
            fwd_step<0, 1, true >(i,     t, alpha, kacc, eyp, mr, yprow, mrow, ea2, pb, sb);
            fwd_step<1, 0, false>(i + 1, t, alpha, kacc, eyp, mr, yprow, mrow, ea2, pb, sb);
            fwd_step<2, 1, false>(i + 2, t, alpha, kacc, eyp, mr, yprow, mrow, ea2, pb, sb);
            fwd_step<3, 0, false>(i + 3, t, alpha, kacc, eyp, mr, yprow, mrow, ea2, pb, sb);
        }

        pb[0][t] = alpha;                     // publish a_mid
        if (t == 0) skacc[0] = kacc;
    } else {
        // ===================== BACKWARD half: steps 1023..513 ===============
        unsigned long long ear2[64];          // EA row t, packed along u
        const float* arow = A + (size_t)t * TAG;
#pragma unroll
        for (int k = 0; k < 64; k++) {
            float e0 = __expf(__ldg(arow + 2 * k));
            float e1 = __expf(__ldg(arow + 2 * k + 1));
            ear2[k] = pack_f32x2(e0, e1);
        }

        float beta = 1.0f;                    // b_{1023} = 1
        int kacc = 0;

        float eyp[4], mr[4];
#pragma unroll
        for (int j = 0; j < 4; j++) {
            eyp[j] = __expf(__ldg(yprow + (SEQLEN - 1 - j) * TAG));
            mr[j]  = __ldg(mrow + (SEQLEN - 1 - j));
        }

        // 511 steps: 127 groups of 4 (i = 1023 .. 516), remainder 515,514,513
        int i = SEQLEN - 1;
        for (; i - 3 > MID + 3; i -= 4) {
            bwd_step<0, 1, true >(i,     t, beta, kacc, eyp, mr, yprow, mrow, ear2, pb, sb);
            bwd_step<1, 0, false>(i - 1, t, beta, kacc, eyp, mr, yprow, mrow, ear2, pb, sb);
            bwd_step<2, 1, false>(i - 2, t, beta, kacc, eyp, mr, yprow, mrow, ear2, pb, sb);
            bwd_step<3, 0, false>(i - 3, t, beta, kacc, eyp, mr, yprow, mrow, ear2, pb, sb);
        }
        // i == 515 here
        bwd_step<0, 1, true >(i,     t, beta, kacc, eyp, mr, yprow, mrow, ear2, pb, sb);
        bwd_step<1, 0, false>(i - 1, t, beta, kacc, eyp, mr, yprow, mrow, ear2, pb, sb);
        bwd_step<2, 1, false>(i - 2, t, beta, kacc, eyp, mr, yprow, mrow, ear2, pb, sb);

        pb[0][t] = beta;                      // publish b_mid
        if (t == 0) skacc[1] = kacc;
    }

    __syncthreads();   // join halves

    // ---- Z = sum_t a[t]*b[t];  logZ = log(Z) - (kf+kb)*ln2 ----
    if (tid < 32) {
        float v = 0.0f;
#pragma unroll
        for (int j = 0; j < 4; j++) {
            int idx = tid + 32 * j;
            v += pbuf[0][0][idx] * pbuf[1][0][idx];
        }
#pragma unroll
        for (int o = 16; o > 0; o >>= 1)
            v += __shfl_xor_sync(0xffffffffu, v, o);
        if (tid == 0) {
            int ktot = skacc[0] + skacc[1];
            g_logZ[b] = logf(v) - (float)ktot * 0.69314718055994530942f;
        }
    }
}

// ---------------- score kernel: 1 CTA per batch ----------------
// y_true arrives as int32 under JAX's default x64-disabled config; handle a
// genuine little-endian int64 layout too by runtime detection (odd 32-bit
// words of the first 128 entries all zero <=> int64, since tags are 0..127).
__global__ void __launch_bounds__(128, 1)
crf_score_kernel(const float* __restrict__ y_pred,
                 const int* __restrict__ y_true32,
                 const float* __restrict__ mask,
                 const float* __restrict__ A)
{
    const int b = blockIdx.x;
    const int t = threadIdx.x;

    __shared__ int s_is64;
    if (t == 0) s_is64 = 1;
    __syncthreads();
    if (y_true32[2 * t + 1] != 0) s_is64 = 0;
    __syncthreads();
    const int stride = s_is64 ? 2 : 1;
    const int* yt = y_true32 + (size_t)b * SEQLEN * stride;

    const float* mrow = mask + (size_t)b * SEQLEN;
    const float* yprow = y_pred + (size_t)b * SEQLEN * TAG;

    float acc = 0.0f;
    for (int s = t; s < SEQLEN; s += 128) {
        int tag = yt[s * stride] & (TAG - 1);
        float m = mrow[s];
        acc += yprow[(size_t)s * TAG + tag] * m;
        if (s + 1 < SEQLEN) {
            int tag2 = yt[(s + 1) * stride] & (TAG - 1);
            float m2 = mrow[s + 1];
            acc += A[tag * TAG + tag2] * m * m2;
        }
    }
    __shared__ float red[128];
    red[t] = acc;
    __syncthreads();
    if (t < 32) {
        float v = red[t] + red[t + 32] + red[t + 64] + red[t + 96];
#pragma unroll
        for (int o = 16; o > 0; o >>= 1)
            v += __shfl_xor_sync(0xffffffffu, v, o);
        if (t == 0) g_score[b] = v;
    }
}

// ---------------- final mean kernel ----------------
__global__ void __launch_bounds__(128, 1)
crf_final_kernel(float* __restrict__ out)
{
    const int t = threadIdx.x;
    float v = g_logZ[t] - g_score[t];
    __shared__ float red[128];
    red[t] = v;
    __syncthreads();
    if (t < 32) {
        float s = red[t] + red[t + 32] + red[t + 64] + red[t + 96];
#pragma unroll
        for (int o = 16; o > 0; o >>= 1)
            s += __shfl_xor_sync(0xffffffffu, s, o);
        if (t == 0) out[0] = s * (1.0f / (float)BATCH);
    }
}

// ---------------- launch ----------------
extern "C" void kernel_launch(void* const* d_in, const int* in_sizes, int n_in,
                              void* d_out, int out_size)
{
    const float* y_pred = nullptr;
    const float* A = nullptr;
    const int* y_true = nullptr;
    const float* mask = nullptr;
    for (int i = 0; i < n_in; i++) {
        long long sz = in_sizes[i];
        if (sz == (long long)BATCH * SEQLEN * TAG) {
            y_pred = (const float*)d_in[i];
        } else if (sz == (long long)TAG * TAG) {
            A = (const float*)d_in[i];
        } else if (sz == (long long)BATCH * SEQLEN) {
            if (!y_true) y_true = (const int*)d_in[i];
            else mask = (const float*)d_in[i];
        }
    }

    crf_forward_kernel<<<BATCH, 256>>>(y_pred, mask, A);
    crf_score_kernel<<<BATCH, 128>>>(y_pred, y_true, mask, A);
    crf_final_kernel<<<1, 128>>>((float*)d_out);
}

// round 8
// speedup vs baseline: 1.2350x; 1.2350x over previous
#include <cuda_runtime.h>
#include <cuda_bf16.h>

// Problem shape (fixed by the dataset)
#define BATCH 128
#define SEQLEN 1024
#define TAG 128
#define MID 512   // forward: steps 1..512 -> alpha_512 ; backward: 1023..513 -> beta_512

// Scratch (allocation-free rule: __device__ globals)
__device__ float g_red[BATCH];   // per-batch (logZ - score)

// ---------------- packed f32x2 helpers (Blackwell FFMA2) ----------------
__device__ __forceinline__ unsigned long long pack_f32x2(float lo, float hi) {
    unsigned long long r;
    asm("mov.b64 %0, {%1, %2};" : "=l"(r) : "f"(lo), "f"(hi));
    return r;
}
__device__ __forceinline__ void unpack_f32x2(float& lo, float& hi, unsigned long long v) {
    asm("mov.b64 {%0, %1}, %2;" : "=f"(lo), "=f"(hi) : "l"(v));
}
__device__ __forceinline__ unsigned long long fma2(unsigned long long a,
                                                   unsigned long long b,
                                                   unsigned long long c) {
    unsigned long long d;
    asm("fma.rn.f32x2 %0, %1, %2, %3;" : "=l"(d) : "l"(a), "l"(b), "l"(c));
    return d;
}

// Named barrier over one 128-thread half (fwd id=1, bwd id=2).
__device__ __forceinline__ void hbar(int id) {
    asm volatile("bar.sync %0, %1;" :: "r"(id), "r"(128) : "memory");
}

// ---- split-u spread phase: warp w, over u in [32w,32w+32), produces the
// partial sums of outputs t = 4l..4l+3 and stores them as one STS.128.
__device__ __forceinline__ void spread(
    const float* __restrict__ vec32,            // asmv + 32*w (16B aligned)
    const unsigned long long (&ea2)[64],        // [j*16+k] = pack over (u0+2k, u0+2k+1) for output j
    float* __restrict__ part, int w, int l)
{
    unsigned long long acc0 = 0ull, acc1 = 0ull, acc2 = 0ull, acc3 = 0ull;
    const ulonglong2* pp = reinterpret_cast<const ulonglong2*>(vec32);
#pragma unroll
    for (int c = 0; c < 8; c++) {
        ulonglong2 v = pp[c];
        acc0 = fma2(v.x, ea2[0 * 16 + 2 * c], acc0);
        acc1 = fma2(v.x, ea2[1 * 16 + 2 * c], acc1);
        acc2 = fma2(v.x, ea2[2 * 16 + 2 * c], acc2);
        acc3 = fma2(v.x, ea2[3 * 16 + 2 * c], acc3);
        acc0 = fma2(v.y, ea2[0 * 16 + 2 * c + 1], acc0);
        acc1 = fma2(v.y, ea2[1 * 16 + 2 * c + 1], acc1);
        acc2 = fma2(v.y, ea2[2 * 16 + 2 * c + 1], acc2);
        acc3 = fma2(v.y, ea2[3 * 16 + 2 * c + 1], acc3);
    }
    float4 po;
    float lo, hi;
    unpack_f32x2(lo, hi, acc0); po.x = lo + hi;
    unpack_f32x2(lo, hi, acc1); po.y = lo + hi;
    unpack_f32x2(lo, hi, acc2); po.z = lo + hi;
    unpack_f32x2(lo, hi, acc3); po.w = lo + hi;
    *reinterpret_cast<float4*>(part + w * TAG + 4 * l) = po;
}

// ---------------- forward step i:  alpha = m ? (EA^T alpha)*ey : alpha -----
template <int SLOT, bool RENORM, bool PREP>
__device__ __forceinline__ void fwd_step(
    int i, int w, int l, int t, float& alpha, int& kacc,
    float (&eyp)[4], float (&mr)[4],
    const float* __restrict__ yprow, const float* __restrict__ mrow,
    const unsigned long long (&ea2)[64],
    float* __restrict__ asmv, float* __restrict__ part, float* __restrict__ sb)
{
    spread(asmv + 32 * w, ea2, part, w, l);
    hbar(1);

    // prefetch (off the serial chain): step i+4's ey/mask
    float ey_n = 0.0f, m_n = 1.0f;
    if (i + 4 <= MID) {
        ey_n = __expf(__ldg(yprow + (i + 4) * TAG));
        m_n  = __ldg(mrow + (i + 4));
    }

    float s = (part[t] + part[TAG + t]) + (part[2 * TAG + t] + part[3 * TAG + t]);
    if (RENORM) {
        // exact power-of-2 rescale; repr published at the PREP step (1 ago)
        int kb = (__float_as_int(sb[0]) >> 23) & 0xff;
        float invc = __int_as_float((254 - kb) << 23);
        kacc += 127 - kb;
        alpha = ((mr[SLOT] > 0.5f) ? s * eyp[SLOT] : alpha) * invc;
    } else {
        alpha = (mr[SLOT] > 0.5f) ? s * eyp[SLOT] : alpha;
    }
    asmv[t] = alpha;
    if (PREP && t == 0) sb[0] = alpha;
    eyp[SLOT] = ey_n;
    mr[SLOT]  = m_n;
    hbar(1);
}

// ---------------- backward step i: beta = m ? EA@(ey_i*beta) : beta --------
// published vector is c_i = ey_i * beta_i ; slot holds (mask_i, ey_pub_i)
// where ey_pub_i = exp(yp_{i-1}) for i-1 > MID, else 1 (final publish = beta).
template <int SLOT, bool RENORM, bool PREP>
__device__ __forceinline__ void bwd_step(
    int i, int w, int l, int t, float& beta, int& kacc,
    float (&eypub)[4], float (&mr)[4],
    const float* __restrict__ yprow, const float* __restrict__ mrow,
    const unsigned long long (&ea2)[64],
    float* __restrict__ asmv, float* __restrict__ part, float* __restrict__ sb)
{
    spread(asmv + 32 * w, ea2, part, w, l);
    hbar(2);

    // prefetch step i-4's (mask, ey_pub)
    float ey_n = 1.0f, m_n = 1.0f;
    if (i - 4 >= MID + 1) {
        m_n  = __ldg(mrow + (i - 4));
        ey_n = (i - 4 > MID + 1) ? __expf(__ldg(yprow + (i - 5) * TAG)) : 1.0f;
    }

    float s = (part[t] + part[TAG + t]) + (part[2 * TAG + t] + part[3 * TAG + t]);
    if (RENORM) {
        int kb = (__float_as_int(sb[0]) >> 23) & 0xff;
        float invc = __int_as_float((254 - kb) << 23);
        kacc += 127 - kb;
        beta = ((mr[SLOT] > 0.5f) ? s : beta) * invc;
    } else {
        beta = (mr[SLOT] > 0.5f) ? s : beta;
    }
    float c = beta * eypub[SLOT];
    asmv[t] = c;
    if (PREP && t == 0) sb[0] = c;
    eypub[SLOT] = ey_n;
    mr[SLOT]    = m_n;
    hbar(2);
}

// ---------------- main kernel: 1 CTA (256 thr) per batch -------------------
// threads 0-127: forward scan; 128-255: backward scan. Named barriers keep
// the halves decoupled. Epilogue: Z = a.b, then the CRF path score, writing
// g_red[b] = logZ_b - score_b.
__global__ void __launch_bounds__(256, 1)
crf_main_kernel(const float* __restrict__ y_pred,
                const int* __restrict__ y_true32,
                const float* __restrict__ mask,
                const float* __restrict__ A)
{
    const int tid = threadIdx.x;
    const int sub = tid >> 7;            // 0 = forward, 1 = backward
    const int t   = tid & (TAG - 1);     // tag index within half
    const int w   = t >> 5;              // warp index within half
    const int l   = t & 31;              // lane
    const int b   = blockIdx.x;

    __shared__ __align__(16) float s_asm[2][TAG];       // published vectors
    __shared__ __align__(16) float s_part[2][4 * TAG];  // split-u partials
    __shared__ float s_sb[2];
    __shared__ int   s_kacc[2];
    __shared__ float s_logZ;
    __shared__ int   s_is64;

    float* asmv = s_asm[sub];
    float* part = s_part[sub];
    float* sb   = &s_sb[sub];

    const float* yprow  = y_pred + (size_t)b * SEQLEN * TAG + t;
    const float* mrow   = mask + (size_t)b * SEQLEN;
    const float* ypbase = y_pred + (size_t)b * SEQLEN * TAG;

    // ---- load EA block (32 u x 4 t) into 64 packed registers ----
    unsigned long long ea2[64];
    const int u0 = 32 * w;
    if (sub == 0) {
        // forward needs EA[u][t_j], t_j = 4l+j
#pragma unroll
        for (int j = 0; j < 4; j++)
#pragma unroll
            for (int k = 0; k < 16; k++) {
                float e0 = __expf(__ldg(A + (u0 + 2 * k)     * TAG + (4 * l + j)));
                float e1 = __expf(__ldg(A + (u0 + 2 * k + 1) * TAG + (4 * l + j)));
                ea2[j * 16 + k] = pack_f32x2(e0, e1);
            }
    } else {
        // backward needs EA[t_j][u]
#pragma unroll
        for (int j = 0; j < 4; j++)
#pragma unroll
            for (int k = 0; k < 16; k++) {
                float e0 = __expf(__ldg(A + (4 * l + j) * TAG + (u0 + 2 * k)));
                float e1 = __expf(__ldg(A + (4 * l + j) * TAG + (u0 + 2 * k + 1)));
                ea2[j * 16 + k] = pack_f32x2(e0, e1);
            }
    }

    int kacc = 0;
    float eyp[4], mr[4];

    if (sub == 0) {
        // ================= FORWARD: steps 1..512 =================
        float alpha = __expf(__ldg(yprow));    // alpha_0
        asmv[t] = alpha;
        if (t == 0) sb[0] = alpha;
#pragma unroll
        for (int j = 0; j < 4; j++) {
            eyp[j] = __expf(__ldg(yprow + (1 + j) * TAG));
            mr[j]  = __ldg(mrow + (1 + j));
        }
        hbar(1);

        for (int i = 1; i <= MID - 3; i += 4) {   // 128 groups
            fwd_step<0, true,  false>(i,     w, l, t, alpha, kacc, eyp, mr, yprow, mrow, ea2, asmv, part, sb);
            fwd_step<1, false, false>(i + 1, w, l, t, alpha, kacc, eyp, mr, yprow, mrow, ea2, asmv, part, sb);
            fwd_step<2, false, false>(i + 2, w, l, t, alpha, kacc, eyp, mr, yprow, mrow, ea2, asmv, part, sb);
            fwd_step<3, false, true >(i + 3, w, l, t, alpha, kacc, eyp, mr, yprow, mrow, ea2, asmv, part, sb);
        }
        if (t == 0) s_kacc[0] = kacc;
    } else {
        // ================= BACKWARD: steps 1023..513 =================
        float beta = 1.0f;
        asmv[t] = __expf(__ldg(yprow + (SEQLEN - 1) * TAG));   // c_1023 = ey_1023
        if (t == 0) sb[0] = asmv[0];
#pragma unroll
        for (int j = 0; j < 4; j++) {
            // slot j <-> step 1023-j: (mask_i, ey_pub_i = exp(yp_{i-1}))
            mr[j]  = __ldg(mrow + (SEQLEN - 1 - j));
            eyp[j] = __expf(__ldg(yprow + (SEQLEN - 2 - j) * TAG));
        }
        hbar(2);

        for (int i = SEQLEN - 1; i >= MID + 7; i -= 4) {   // 127 groups: 1023..516
            bwd_step<0, true,  false>(i,     w, l, t, beta, kacc, eyp, mr, yprow, mrow, ea2, asmv, part, sb);
            bwd_step<1, false, false>(i - 1, w, l, t, beta, kacc, eyp, mr, yprow, mrow, ea2, asmv, part, sb);
            bwd_step<2, false, false>(i - 2, w, l, t, beta, kacc, eyp, mr, yprow, mrow, ea2, asmv, part, sb);
            bwd_step<3, false, true >(i - 3, w, l, t, beta, kacc, eyp, mr, yprow, mrow, ea2, asmv, part, sb);
        }
        // remainder: steps 515, 514, 513 (slots 0,1,2)
        bwd_step<0, true,  false>(MID + 3, w, l, t, beta, kacc, eyp, mr, yprow, mrow, ea2, asmv, part, sb);
        bwd_step<1, false, false>(MID + 2, w, l, t, beta, kacc, eyp, mr, yprow, mrow, ea2, asmv, part, sb);
        bwd_step<2, false, false>(MID + 1, w, l, t, beta, kacc, eyp, mr, yprow, mrow, ea2, asmv, part, sb);
        // asmv now holds beta_512 (ey_pub for step 513 is 1)
        if (t == 0) s_kacc[1] = kacc;
    }

    __syncthreads();   // join halves

    // ---- logZ = log(sum_t a_mid[t]*b_mid[t]) - (kf+kb)*ln2 ----
    if (tid < 32) {
        float v = 0.0f;
#pragma unroll
        for (int j = 0; j < 4; j++)
            v += s_asm[0][tid + 32 * j] * s_asm[1][tid + 32 * j];
#pragma unroll
        for (int o = 16; o > 0; o >>= 1)
            v += __shfl_xor_sync(0xffffffffu, v, o);
        if (tid == 0)
            s_logZ = logf(v) - (float)(s_kacc[0] + s_kacc[1]) * 0.69314718055994530942f;
    }

    // ---- path score (fused; all 256 threads) ----
    // y_true is int32 under JAX default x64-disabled; detect a genuine LE
    // int64 layout (odd words of first 128 entries all zero <=> int64).
    if (tid == 0) s_is64 = 1;
    __syncthreads();
    if (tid < 128 && y_true32[2 * tid + 1] != 0) s_is64 = 0;
    __syncthreads();
    const int stride = s_is64 ? 2 : 1;
    const int* yt = y_true32 + (size_t)b * SEQLEN * stride;

    float acc = 0.0f;
    for (int s = tid; s < SEQLEN; s += 256) {
        int tag = yt[s * stride] & (TAG - 1);
        float m = mrow[s];
        acc += ypbase[(size_t)s * TAG + tag] * m;
        if (s + 1 < SEQLEN) {
            int tag2 = yt[(s + 1) * stride] & (TAG - 1);
            acc += A[tag * TAG + tag2] * m * mrow[s + 1];
        }
    }
    float* red = &s_part[0][0];   // 256-float scratch (scan is done)
    red[tid] = acc;
    __syncthreads();
    if (tid < 32) {
        float v = 0.0f;
#pragma unroll
        for (int j = 0; j < 8; j++) v += red[tid + 32 * j];
#pragma unroll
        for (int o = 16; o > 0; o >>= 1)
            v += __shfl_xor_sync(0xffffffffu, v, o);
        if (tid == 0) g_red[b] = s_logZ - v;
    }
}

// ---------------- final mean kernel ----------------
__global__ void __launch_bounds__(128, 1)
crf_final_kernel(float* __restrict__ out)
{
    const int t = threadIdx.x;
    float v = g_red[t];
    __shared__ float red[128];
    red[t] = v;
    __syncthreads();
    if (t < 32) {
        float s = red[t] + red[t + 32] + red[t + 64] + red[t + 96];
#pragma unroll
        for (int o = 16; o > 0; o >>= 1)
            s += __shfl_xor_sync(0xffffffffu, s, o);
        if (t == 0) out[0] = s * (1.0f / (float)BATCH);
    }
}

// ---------------- launch ----------------
extern "C" void kernel_launch(void* const* d_in, const int* in_sizes, int n_in,
                              void* d_out, int out_size)
{
    const float* y_pred = nullptr;
    const float* A = nullptr;
    const int* y_true = nullptr;
    const float* mask = nullptr;
    for (int i = 0; i < n_in; i++) {
        long long sz = in_sizes[i];
        if (sz == (long long)BATCH * SEQLEN * TAG) {
            y_pred = (const float*)d_in[i];
        } else if (sz == (long long)TAG * TAG) {
            A = (const float*)d_in[i];
        } else if (sz == (long long)BATCH * SEQLEN) {
            if (!y_true) y_true = (const int*)d_in[i];
            else mask = (const float*)d_in[i];
        }
    }

    crf_main_kernel<<<BATCH, 256>>>(y_pred, y_true, mask, A);
    crf_final_kernel<<<1, 128>>>((float*)d_out);
}